// round 1
// baseline (speedup 1.0000x reference)
#include <cuda_runtime.h>

// ============================================================================
// ShiftedWindowAttention  (Swin attention block)
//   B=32, H=W=56, C=384, heads=12, dh=32, window 7x7 (T=49), shift (3,3)
//   Pipeline:
//     K1: gather(roll + window partition) + QKV GEMM (+bias) -> g_qkv
//     K2: per (window, head): S = qk^T*scale + relposbias + shiftmask,
//         softmax, O = S @ v -> g_att  ([Bn, T, C] layout)
//     K3: proj GEMM (+bias) + scatter(window reverse + roll back) -> d_out
// ============================================================================

#define B_    32
#define HH    56
#define CC    384
#define NH    12
#define DH    32
#define T_    49
#define NWIN  64                 // 8x8 windows per image
#define BN_TOT (B_ * NWIN)       // 2048
#define M_TOT  (BN_TOT * T_)     // 100352

// scratch (device globals; no runtime allocation allowed)
__device__ float g_qkv[(size_t)BN_TOT * 3 * NH * T_ * DH];  // [wi][3][head][t][d]
__device__ float g_att[(size_t)M_TOT * CC];                 // [m][c]

// ---------------------------------------------------------------------------
// GEMM tiling
// ---------------------------------------------------------------------------
constexpr int BM = 128;
constexpr int BNt = 64;
constexpr int BK = 16;
constexpr int TM = 8;
constexpr int TN = 4;

// ---------------------------------------------------------------------------
// K1: QKV GEMM with gathered A (roll -3,-3 + window partition)
//     C[m][n] = sum_k x_gathered[m][k] * Wqkv[n][k] + bias[n]
//     scatter into g_qkv as [wi][which][head][t][d]
// ---------------------------------------------------------------------------
__global__ __launch_bounds__(256) void qkv_gemm_kernel(
    const float* __restrict__ x,        // [B,56,56,384]
    const float* __restrict__ w,        // [1152, 384]
    const float* __restrict__ bias)     // [1152]
{
    __shared__ float As[BK][BM + 4];
    __shared__ float Bs[BK][BNt + 4];
    __shared__ int   rbase[BM];

    const int tid = threadIdx.x;
    const int m0 = blockIdx.y * BM;
    const int n0 = blockIdx.x * BNt;
    const int tx = tid & 15;
    const int ty = tid >> 4;

    if (tid < BM) {
        int m = m0 + tid;
        int wi = m / T_, t = m - wi * T_;
        int b = wi >> 6, wloc = wi & 63;
        int wr = wloc >> 3, wc = wloc & 7;
        int th = t / 7, tw = t - th * 7;
        int i = wr * 7 + th, j = wc * 7 + tw;
        int si = i + 3; if (si >= HH) si -= HH;   // roll(-3)
        int sj = j + 3; if (sj >= HH) sj -= HH;
        rbase[tid] = ((b * HH + si) * HH + sj) * CC;
    }
    __syncthreads();

    float acc[TM][TN];
#pragma unroll
    for (int i = 0; i < TM; i++)
#pragma unroll
        for (int j = 0; j < TN; j++) acc[i][j] = 0.f;

    for (int k0 = 0; k0 < CC; k0 += BK) {
        // load A tile: BM x BK (gathered rows, 16 contiguous floats each)
#pragma unroll
        for (int i = 0; i < (BM * BK) / 256; i++) {
            int e = i * 256 + tid;
            int k = e & 15, mm = e >> 4;
            As[k][mm] = x[rbase[mm] + k0 + k];
        }
        // load B tile: BK x BN  (w is [n][k] row-major)
#pragma unroll
        for (int i = 0; i < (BK * BNt) / 256; i++) {
            int e = i * 256 + tid;
            int k = e & 15, nn = e >> 4;
            Bs[k][nn] = w[(size_t)(n0 + nn) * CC + k0 + k];
        }
        __syncthreads();

#pragma unroll
        for (int k = 0; k < BK; k++) {
            float a[TM], b2[TN];
#pragma unroll
            for (int i = 0; i < TM; i++) a[i] = As[k][ty * TM + i];
#pragma unroll
            for (int j = 0; j < TN; j++) b2[j] = Bs[k][tx * TN + j];
#pragma unroll
            for (int i = 0; i < TM; i++)
#pragma unroll
                for (int j = 0; j < TN; j++) acc[i][j] += a[i] * b2[j];
        }
        __syncthreads();
    }

    // epilogue: +bias, scatter into [wi][which][head][t][d]
#pragma unroll
    for (int i = 0; i < TM; i++) {
        int m = m0 + ty * TM + i;
        int wi = m / T_, t = m - wi * T_;
#pragma unroll
        for (int j = 0; j < TN; j++) {
            int n = n0 + tx * TN + j;
            int which = n / CC;
            int rem = n - which * CC;
            int head = rem >> 5;
            int d = rem & 31;
            size_t idx = ((((size_t)wi * 3 + which) * NH + head) * T_ + t) * DH + d;
            g_qkv[idx] = acc[i][j] + bias[n];
        }
    }
}

// ---------------------------------------------------------------------------
// K2: attention per (window, head)
// ---------------------------------------------------------------------------
__global__ __launch_bounds__(256) void attn_kernel(
    const float* __restrict__ table)    // [169, 12]
{
    __shared__ float qs[T_][DH];
    __shared__ float ks[T_][DH + 1];
    __shared__ float vs[T_][DH + 1];
    __shared__ float S[T_][T_ + 1];
    __shared__ float biasc[169];
    __shared__ int   th_[T_], tw_[T_], reg_[T_];

    const int tid = threadIdx.x;
    const int wh = blockIdx.x;
    const int wi = wh / NH;
    const int head = wh - wi * NH;

    const int wloc = wi & 63;
    const int wr = wloc >> 3, wc = wloc & 7;

    // token meta + shift-mask region
    if (tid < T_) {
        int th = tid / 7, tw = tid - th * 7;
        th_[tid] = th; tw_[tid] = tw;
        int i = wr * 7 + th, j = wc * 7 + tw;     // coords in shifted image
        int hr = (i < 49) ? 0 : ((i < 53) ? 1 : 2);
        int wg = (j < 49) ? 0 : ((j < 53) ? 1 : 2);
        reg_[tid] = hr * 3 + wg;
    }
    if (tid < 169) biasc[tid] = table[tid * NH + head];

    // load q (scaled), k, v
    const size_t qb = (((size_t)wi * 3 + 0) * NH + head) * (T_ * DH);
    const float* gq = g_qkv + qb;
    const float* gk = gq + (size_t)NH * T_ * DH;
    const float* gv = gk + (size_t)NH * T_ * DH;
    for (int e = tid; e < T_ * DH; e += 256) {
        int t = e >> 5, d = e & 31;
        qs[t][d] = gq[e] * 0.17677669529663687f;   // dh^-0.5
        ks[t][d] = gk[e];
        vs[t][d] = gv[e];
    }
    __syncthreads();

    // S = q k^T + bias + mask
    for (int e = tid; e < T_ * T_; e += 256) {
        int t = e / T_, s = e - t * T_;
        float a = 0.f;
#pragma unroll
        for (int d = 0; d < DH; d++) a += qs[t][d] * ks[s][d];
        int rp = (th_[t] - th_[s] + 6) * 13 + (tw_[t] - tw_[s] + 6);
        a += biasc[rp];
        if (reg_[t] != reg_[s]) a -= 100.0f;
        S[t][s] = a;
    }
    __syncthreads();

    // softmax per row
    if (tid < T_) {
        float mx = -1e30f;
#pragma unroll 7
        for (int s = 0; s < T_; s++) mx = fmaxf(mx, S[tid][s]);
        float sum = 0.f;
#pragma unroll 7
        for (int s = 0; s < T_; s++) {
            float e2 = __expf(S[tid][s] - mx);
            S[tid][s] = e2;
            sum += e2;
        }
        float inv = 1.f / sum;
#pragma unroll 7
        for (int s = 0; s < T_; s++) S[tid][s] *= inv;
    }
    __syncthreads();

    // O = P @ V  -> g_att [m][c] with c = head*32 + d
    for (int o = tid; o < T_ * DH; o += 256) {
        int t = o >> 5, d = o & 31;
        float a = 0.f;
#pragma unroll 7
        for (int s = 0; s < T_; s++) a += S[t][s] * vs[s][d];
        g_att[((size_t)wi * T_ + t) * CC + head * DH + d] = a;
    }
}

// ---------------------------------------------------------------------------
// K3: proj GEMM + scatter (window reverse + roll +3,+3)
// ---------------------------------------------------------------------------
__global__ __launch_bounds__(256) void proj_gemm_kernel(
    const float* __restrict__ w,        // [384, 384]
    const float* __restrict__ bias,     // [384]
    float* __restrict__ out)            // [B,56,56,384]
{
    __shared__ float As[BK][BM + 4];
    __shared__ float Bs[BK][BNt + 4];

    const int tid = threadIdx.x;
    const int m0 = blockIdx.y * BM;
    const int n0 = blockIdx.x * BNt;
    const int tx = tid & 15;
    const int ty = tid >> 4;

    float acc[TM][TN];
#pragma unroll
    for (int i = 0; i < TM; i++)
#pragma unroll
        for (int j = 0; j < TN; j++) acc[i][j] = 0.f;

    for (int k0 = 0; k0 < CC; k0 += BK) {
#pragma unroll
        for (int i = 0; i < (BM * BK) / 256; i++) {
            int e = i * 256 + tid;
            int k = e & 15, mm = e >> 4;
            As[k][mm] = g_att[(size_t)(m0 + mm) * CC + k0 + k];
        }
#pragma unroll
        for (int i = 0; i < (BK * BNt) / 256; i++) {
            int e = i * 256 + tid;
            int k = e & 15, nn = e >> 4;
            Bs[k][nn] = w[(size_t)(n0 + nn) * CC + k0 + k];
        }
        __syncthreads();

#pragma unroll
        for (int k = 0; k < BK; k++) {
            float a[TM], b2[TN];
#pragma unroll
            for (int i = 0; i < TM; i++) a[i] = As[k][ty * TM + i];
#pragma unroll
            for (int j = 0; j < TN; j++) b2[j] = Bs[k][tx * TN + j];
#pragma unroll
            for (int i = 0; i < TM; i++)
#pragma unroll
                for (int j = 0; j < TN; j++) acc[i][j] += a[i] * b2[j];
        }
        __syncthreads();
    }

    // epilogue: +bias, window-reverse + roll(+3,+3) scatter
#pragma unroll
    for (int i = 0; i < TM; i++) {
        int m = m0 + ty * TM + i;
        int wi = m / T_, t = m - wi * T_;
        int b = wi >> 6, wloc = wi & 63;
        int wr = wloc >> 3, wc = wloc & 7;
        int th = t / 7, tw = t - th * 7;
        int ii = wr * 7 + th, jj = wc * 7 + tw;
        int oi = ii + 3; if (oi >= HH) oi -= HH;
        int oj = jj + 3; if (oj >= HH) oj -= HH;
        float* orow = out + ((size_t)(b * HH + oi) * HH + oj) * CC;
#pragma unroll
        for (int j = 0; j < TN; j++) {
            int n = n0 + tx * TN + j;
            orow[n] = acc[i][j] + bias[n];
        }
    }
}

// ---------------------------------------------------------------------------
extern "C" void kernel_launch(void* const* d_in, const int* in_sizes, int n_in,
                              void* d_out, int out_size)
{
    const float* x     = (const float*)d_in[0];
    const float* qkvw  = (const float*)d_in[1];
    const float* qkvb  = (const float*)d_in[2];
    const float* projw = (const float*)d_in[3];
    const float* projb = (const float*)d_in[4];
    const float* table = (const float*)d_in[5];
    float* out = (float*)d_out;

    dim3 g1((3 * CC) / BNt, M_TOT / BM);   // (18, 784)
    qkv_gemm_kernel<<<g1, 256>>>(x, qkvw, qkvb);

    attn_kernel<<<BN_TOT * NH, 256>>>(table);

    dim3 g3(CC / BNt, M_TOT / BM);         // (6, 784)
    proj_gemm_kernel<<<g3, 256>>>(projw, projb, out);
}

// round 2
// speedup vs baseline: 2.2443x; 2.2443x over previous
#include <cuda_runtime.h>
#include <cstdint>

// ============================================================================
// ShiftedWindowAttention — Round 2: TF32 mma.sync GEMMs
//   K1: gather(roll+window) + QKV GEMM (tf32 tensor) -> g_qkv
//   K2: per (window, head) attention (fp32, unchanged)
//   K3: proj GEMM (tf32 tensor) + scatter(window reverse + roll)
// ============================================================================

#define B_    32
#define HH    56
#define CC    384
#define NH    12
#define DH    32
#define T_    49
#define NWIN  64
#define BN_TOT (B_ * NWIN)       // 2048
#define M_TOT  (BN_TOT * T_)     // 100352

__device__ float g_qkv[(size_t)BN_TOT * 3 * NH * T_ * DH];  // [wi][3][head][t][d]
__device__ float g_att[(size_t)M_TOT * CC];                 // [m][c]

// ---------------------------------------------------------------------------
// tf32 helpers
// ---------------------------------------------------------------------------
__device__ __forceinline__ uint32_t f2tf32(float f) {
    uint32_t r;
    asm("cvt.rna.tf32.f32 %0, %1;" : "=r"(r) : "f"(f));
    return r;
}

__device__ __forceinline__ void mma_tf32(float c[4],
                                         uint32_t a0, uint32_t a1, uint32_t a2, uint32_t a3,
                                         uint32_t b0, uint32_t b1) {
    asm volatile(
        "mma.sync.aligned.m16n8k8.row.col.f32.tf32.tf32.f32 "
        "{%0,%1,%2,%3}, {%4,%5,%6,%7}, {%8,%9}, {%0,%1,%2,%3};"
        : "+f"(c[0]), "+f"(c[1]), "+f"(c[2]), "+f"(c[3])
        : "r"(a0), "r"(a1), "r"(a2), "r"(a3), "r"(b0), "r"(b1));
}

// GEMM tiling: block 128x128x32, 8 warps (2x4), warp tile 64x32
constexpr int BMg = 128;
constexpr int BNg = 128;
constexpr int BKg = 32;
constexpr int ASTR = BMg + 4;   // 132 (u32)
constexpr int BSTR = BNg + 4;   // 132

// ---------------------------------------------------------------------------
// K1: QKV GEMM, A gathered (roll -3,-3 + window partition)
// ---------------------------------------------------------------------------
__global__ __launch_bounds__(256) void qkv_gemm_tf32(
    const float* __restrict__ x,        // [B,56,56,384]
    const float* __restrict__ w,        // [1152, 384]
    const float* __restrict__ bias)     // [1152]
{
    __shared__ uint32_t As[BKg * ASTR];   // [k][m] tf32
    __shared__ uint32_t Bs[BKg * BSTR];   // [k][n] tf32
    __shared__ int      rbase[BMg];

    const int tid  = threadIdx.x;
    const int lane = tid & 31;
    const int warp = tid >> 5;
    const int m0 = blockIdx.y * BMg;
    const int n0 = blockIdx.x * BNg;

    const int warpRow = warp >> 2;          // 0..1
    const int warpCol = warp & 3;           // 0..3
    const int wm = warpRow * 64;
    const int wn = warpCol * 32;
    const int gq = lane >> 2;               // 0..7
    const int tq = lane & 3;                // 0..3

    // gathered A row bases
    if (tid < BMg) {
        int m = m0 + tid;
        int wi = m / T_, t = m - wi * T_;
        int b = wi >> 6, wloc = wi & 63;
        int wr = wloc >> 3, wc = wloc & 7;
        int th = t / 7, tw = t - th * 7;
        int si = wr * 7 + th + 3; if (si >= HH) si -= HH;
        int sj = wc * 7 + tw + 3; if (sj >= HH) sj -= HH;
        rbase[tid] = ((b * HH + si) * HH + sj) * CC;
    }
    __syncthreads();

    float c[4][4][4];
#pragma unroll
    for (int i = 0; i < 4; i++)
#pragma unroll
        for (int j = 0; j < 4; j++)
#pragma unroll
            for (int r = 0; r < 4; r++) c[i][j][r] = 0.f;

    // loader slot assignment (1024 float4 slots each for A and B)
    const int slotA_m = tid >> 1;                 // with 2 slots/thread/iter pattern below
    for (int k0 = 0; k0 < CC; k0 += BKg) {
        // ---- load A tile: 128 rows x 32 k  (8 float4 per row) ----
#pragma unroll
        for (int it = 0; it < 4; it++) {
            int slot = it * 256 + tid;            // 0..1023
            int mm = slot >> 3, q = slot & 7;     // row, float4 idx
            const float4 v = *(const float4*)(x + rbase[mm] + k0 + q * 4);
            int kk = q * 4;
            As[(kk + 0) * ASTR + mm] = f2tf32(v.x);
            As[(kk + 1) * ASTR + mm] = f2tf32(v.y);
            As[(kk + 2) * ASTR + mm] = f2tf32(v.z);
            As[(kk + 3) * ASTR + mm] = f2tf32(v.w);
        }
        // ---- load B tile: 128 n x 32 k ----
#pragma unroll
        for (int it = 0; it < 4; it++) {
            int slot = it * 256 + tid;
            int nn = slot >> 3, q = slot & 7;
            const float4 v = *(const float4*)(w + (size_t)(n0 + nn) * CC + k0 + q * 4);
            int kk = q * 4;
            Bs[(kk + 0) * BSTR + nn] = f2tf32(v.x);
            Bs[(kk + 1) * BSTR + nn] = f2tf32(v.y);
            Bs[(kk + 2) * BSTR + nn] = f2tf32(v.z);
            Bs[(kk + 3) * BSTR + nn] = f2tf32(v.w);
        }
        __syncthreads();

#pragma unroll
        for (int ks = 0; ks < 4; ks++) {
            const int kk = ks * 8;
            // B fragments for 4 n-tiles
            uint32_t bf[4][2];
#pragma unroll
            for (int j = 0; j < 4; j++) {
                int ncol = wn + j * 8 + gq;
                bf[j][0] = Bs[(kk + tq) * BSTR + ncol];
                bf[j][1] = Bs[(kk + tq + 4) * BSTR + ncol];
            }
#pragma unroll
            for (int i = 0; i < 4; i++) {
                int mrow = wm + i * 16 + gq;
                uint32_t a0 = As[(kk + tq) * ASTR + mrow];
                uint32_t a1 = As[(kk + tq) * ASTR + mrow + 8];
                uint32_t a2 = As[(kk + tq + 4) * ASTR + mrow];
                uint32_t a3 = As[(kk + tq + 4) * ASTR + mrow + 8];
#pragma unroll
                for (int j = 0; j < 4; j++)
                    mma_tf32(c[i][j], a0, a1, a2, a3, bf[j][0], bf[j][1]);
            }
        }
        __syncthreads();
    }

    // epilogue: +bias, scatter to g_qkv [wi][3][head][t][d]
#pragma unroll
    for (int i = 0; i < 4; i++) {
        int m_lo = m0 + wm + i * 16 + gq;
        int m_hi = m_lo + 8;
        int wi_lo = m_lo / T_, t_lo = m_lo - wi_lo * T_;
        int wi_hi = m_hi / T_, t_hi = m_hi - wi_hi * T_;
#pragma unroll
        for (int j = 0; j < 4; j++) {
#pragma unroll
            for (int e = 0; e < 2; e++) {
                int n = n0 + wn + j * 8 + 2 * tq + e;
                int which = n / CC;
                int rem = n - which * CC;
                int head = rem >> 5, d = rem & 31;
                float bv = bias[n];
                size_t i_lo = ((((size_t)wi_lo * 3 + which) * NH + head) * T_ + t_lo) * DH + d;
                size_t i_hi = ((((size_t)wi_hi * 3 + which) * NH + head) * T_ + t_hi) * DH + d;
                g_qkv[i_lo] = c[i][j][e] + bv;
                g_qkv[i_hi] = c[i][j][e + 2] + bv;
            }
        }
    }
    (void)slotA_m;
}

// ---------------------------------------------------------------------------
// K2: attention per (window, head)  — fp32, unchanged from round 1
// ---------------------------------------------------------------------------
__global__ __launch_bounds__(256) void attn_kernel(
    const float* __restrict__ table)    // [169, 12]
{
    __shared__ float qs[T_][DH];
    __shared__ float ks[T_][DH + 1];
    __shared__ float vs[T_][DH + 1];
    __shared__ float S[T_][T_ + 1];
    __shared__ float biasc[169];
    __shared__ int   th_[T_], tw_[T_], reg_[T_];

    const int tid = threadIdx.x;
    const int wh = blockIdx.x;
    const int wi = wh / NH;
    const int head = wh - wi * NH;

    const int wloc = wi & 63;
    const int wr = wloc >> 3, wc = wloc & 7;

    if (tid < T_) {
        int th = tid / 7, tw = tid - th * 7;
        th_[tid] = th; tw_[tid] = tw;
        int i = wr * 7 + th, j = wc * 7 + tw;
        int hr = (i < 49) ? 0 : ((i < 53) ? 1 : 2);
        int wg = (j < 49) ? 0 : ((j < 53) ? 1 : 2);
        reg_[tid] = hr * 3 + wg;
    }
    if (tid < 169) biasc[tid] = table[tid * NH + head];

    const size_t qb = (((size_t)wi * 3 + 0) * NH + head) * (T_ * DH);
    const float* gq = g_qkv + qb;
    const float* gk = gq + (size_t)NH * T_ * DH;
    const float* gv = gk + (size_t)NH * T_ * DH;
    for (int e = tid; e < T_ * DH; e += 256) {
        int t = e >> 5, d = e & 31;
        qs[t][d] = gq[e] * 0.17677669529663687f;
        ks[t][d] = gk[e];
        vs[t][d] = gv[e];
    }
    __syncthreads();

    for (int e = tid; e < T_ * T_; e += 256) {
        int t = e / T_, s = e - t * T_;
        float a = 0.f;
#pragma unroll
        for (int d = 0; d < DH; d++) a += qs[t][d] * ks[s][d];
        int rp = (th_[t] - th_[s] + 6) * 13 + (tw_[t] - tw_[s] + 6);
        a += biasc[rp];
        if (reg_[t] != reg_[s]) a -= 100.0f;
        S[t][s] = a;
    }
    __syncthreads();

    if (tid < T_) {
        float mx = -1e30f;
#pragma unroll 7
        for (int s = 0; s < T_; s++) mx = fmaxf(mx, S[tid][s]);
        float sum = 0.f;
#pragma unroll 7
        for (int s = 0; s < T_; s++) {
            float e2 = __expf(S[tid][s] - mx);
            S[tid][s] = e2;
            sum += e2;
        }
        float inv = 1.f / sum;
#pragma unroll 7
        for (int s = 0; s < T_; s++) S[tid][s] *= inv;
    }
    __syncthreads();

    for (int o = tid; o < T_ * DH; o += 256) {
        int t = o >> 5, d = o & 31;
        float a = 0.f;
#pragma unroll 7
        for (int s = 0; s < T_; s++) a += S[t][s] * vs[s][d];
        g_att[((size_t)wi * T_ + t) * CC + head * DH + d] = a;
    }
}

// ---------------------------------------------------------------------------
// K3: proj GEMM (tf32) + scatter (window reverse + roll +3,+3)
// ---------------------------------------------------------------------------
__global__ __launch_bounds__(256) void proj_gemm_tf32(
    const float* __restrict__ w,        // [384, 384]
    const float* __restrict__ bias,     // [384]
    float* __restrict__ out)            // [B,56,56,384]
{
    __shared__ uint32_t As[BKg * ASTR];
    __shared__ uint32_t Bs[BKg * BSTR];

    const int tid  = threadIdx.x;
    const int lane = tid & 31;
    const int warp = tid >> 5;
    const int m0 = blockIdx.y * BMg;
    const int n0 = blockIdx.x * BNg;

    const int warpRow = warp >> 2;
    const int warpCol = warp & 3;
    const int wm = warpRow * 64;
    const int wn = warpCol * 32;
    const int gq = lane >> 2;
    const int tq = lane & 3;

    float c[4][4][4];
#pragma unroll
    for (int i = 0; i < 4; i++)
#pragma unroll
        for (int j = 0; j < 4; j++)
#pragma unroll
            for (int r = 0; r < 4; r++) c[i][j][r] = 0.f;

    for (int k0 = 0; k0 < CC; k0 += BKg) {
#pragma unroll
        for (int it = 0; it < 4; it++) {
            int slot = it * 256 + tid;
            int mm = slot >> 3, q = slot & 7;
            const float4 v = *(const float4*)(g_att + (size_t)(m0 + mm) * CC + k0 + q * 4);
            int kk = q * 4;
            As[(kk + 0) * ASTR + mm] = f2tf32(v.x);
            As[(kk + 1) * ASTR + mm] = f2tf32(v.y);
            As[(kk + 2) * ASTR + mm] = f2tf32(v.z);
            As[(kk + 3) * ASTR + mm] = f2tf32(v.w);
        }
#pragma unroll
        for (int it = 0; it < 4; it++) {
            int slot = it * 256 + tid;
            int nn = slot >> 3, q = slot & 7;
            const float4 v = *(const float4*)(w + (size_t)(n0 + nn) * CC + k0 + q * 4);
            int kk = q * 4;
            Bs[(kk + 0) * BSTR + nn] = f2tf32(v.x);
            Bs[(kk + 1) * BSTR + nn] = f2tf32(v.y);
            Bs[(kk + 2) * BSTR + nn] = f2tf32(v.z);
            Bs[(kk + 3) * BSTR + nn] = f2tf32(v.w);
        }
        __syncthreads();

#pragma unroll
        for (int ks = 0; ks < 4; ks++) {
            const int kk = ks * 8;
            uint32_t bf[4][2];
#pragma unroll
            for (int j = 0; j < 4; j++) {
                int ncol = wn + j * 8 + gq;
                bf[j][0] = Bs[(kk + tq) * BSTR + ncol];
                bf[j][1] = Bs[(kk + tq + 4) * BSTR + ncol];
            }
#pragma unroll
            for (int i = 0; i < 4; i++) {
                int mrow = wm + i * 16 + gq;
                uint32_t a0 = As[(kk + tq) * ASTR + mrow];
                uint32_t a1 = As[(kk + tq) * ASTR + mrow + 8];
                uint32_t a2 = As[(kk + tq + 4) * ASTR + mrow];
                uint32_t a3 = As[(kk + tq + 4) * ASTR + mrow + 8];
#pragma unroll
                for (int j = 0; j < 4; j++)
                    mma_tf32(c[i][j], a0, a1, a2, a3, bf[j][0], bf[j][1]);
            }
        }
        __syncthreads();
    }

    // epilogue: +bias, window-reverse + roll(+3,+3) scatter
#pragma unroll
    for (int i = 0; i < 4; i++) {
#pragma unroll
        for (int e = 0; e < 2; e++) {
            int m = m0 + wm + i * 16 + gq + e * 8;
            int wi = m / T_, t = m - wi * T_;
            int b = wi >> 6, wloc = wi & 63;
            int wr = wloc >> 3, wc = wloc & 7;
            int th = t / 7, tw = t - th * 7;
            int oi = wr * 7 + th + 3; if (oi >= HH) oi -= HH;
            int oj = wc * 7 + tw + 3; if (oj >= HH) oj -= HH;
            float* orow = out + ((size_t)(b * HH + oi) * HH + oj) * CC;
#pragma unroll
            for (int j = 0; j < 4; j++) {
                int n = n0 + wn + j * 8 + 2 * tq;
                orow[n]     = c[i][j][e * 2]     + bias[n];
                orow[n + 1] = c[i][j][e * 2 + 1] + bias[n + 1];
            }
        }
    }
}

// ---------------------------------------------------------------------------
extern "C" void kernel_launch(void* const* d_in, const int* in_sizes, int n_in,
                              void* d_out, int out_size)
{
    const float* x     = (const float*)d_in[0];
    const float* qkvw  = (const float*)d_in[1];
    const float* qkvb  = (const float*)d_in[2];
    const float* projw = (const float*)d_in[3];
    const float* projb = (const float*)d_in[4];
    const float* table = (const float*)d_in[5];
    float* out = (float*)d_out;

    dim3 g1((3 * CC) / BNg, M_TOT / BMg);   // (9, 784)
    qkv_gemm_tf32<<<g1, 256>>>(x, qkvw, qkvb);

    attn_kernel<<<BN_TOT * NH, 256>>>(table);

    dim3 g3(CC / BNg, M_TOT / BMg);         // (3, 784)
    proj_gemm_tf32<<<g3, 256>>>(projw, projb, out);
}